// round 12
// baseline (speedup 1.0000x reference)
#include <cuda_runtime.h>
#include <cstdint>

// RandomShiftsAug == integer pixel shift with edge clamp (reference's bilinear
// weights are exactly zero given its linspace/scale arithmetic):
//   out[n,c,j,i] = x[n,c, clamp(j+sy-PAD,0,H-1), clamp(i+sx-PAD,0,W-1)]
//
// R12 = R3 (best: 36.3us kernel) with phase 1's LDG->STS register round-trip
// replaced by cp.async.cg (LDGSTS). The R3 profile (occ 68%, issue 23%, DRAM
// 62%) says warps sit in long-scoreboard on the staged loads; cp.async issues
// all 7 copies without a register dependency and waits once. Same SMEM/CTA
// shape as R3 (32KB, 7 CTAs/SM) so this isolates the one change. Stores stay
// default (st.global.cs regressed in R11).

#define C_   4
#define W_   84
#define H_   84
#define PAD_ 4
#define W4_  21
#define RP_  96          // padded row: [0..3] pad | [4..87] data | [88..91] pad
#define NBLK (H_ * W4_)  // 1764 float4 per plane

__device__ __forceinline__ void cp16(float* dst, const float4* src) {
    uint32_t d = (uint32_t)__cvta_generic_to_shared(dst);
    asm volatile("cp.async.cg.shared.global [%0], [%1], 16;"
                 :: "r"(d), "l"(src) : "memory");
}

__global__ void __launch_bounds__(256) shift_smem_kernel(
    const float* __restrict__ x,
    const int*   __restrict__ shift,
    float*       __restrict__ out)
{
    __shared__ float s[H_ * RP_];   // 32256 B

    const int nc  = blockIdx.x;     // n*C + c
    const int n   = nc >> 2;
    const int tid = threadIdx.x;

    int2 sh = __ldg(reinterpret_cast<const int2*>(shift) + n);
    const int sx = sh.x - PAD_;     // [-4, 4]
    const int sy = sh.y - PAD_;

    // ---- phase 1: cp.async stage GMEM -> SMEM (no register round-trip) ----
    const float4* in4 = reinterpret_cast<const float4*>(x) + nc * NBLK;
    #pragma unroll
    for (int it = 0; it < 7; ++it) {
        int m = tid + it * 256;
        if (m < NBLK) {
            int row = m / W4_;
            int w4  = m - row * W4_;
            cp16(&s[row * RP_ + 4 + 4 * w4], in4 + m);
        }
    }
    asm volatile("cp.async.commit_group;" ::: "memory");
    asm volatile("cp.async.wait_group 0;" ::: "memory");
    __syncthreads();

    // ---- phase 2: edge-clamp pads ----
    if (tid < H_) {
        float* row = s + tid * RP_;
        float l = row[4];
        float r = row[87];
        reinterpret_cast<float4*>(row)[0]  = make_float4(l, l, l, l);  // 0..3
        reinterpret_cast<float4*>(row)[22] = make_float4(r, r, r, r);  // 88..91
    }
    __syncthreads();

    // ---- phase 3: swizzle from SMEM, coalesced float4 stores ----
    float4* out4 = reinterpret_cast<float4*>(out) + nc * NBLK;
    #pragma unroll
    for (int it = 0; it < 7; ++it) {
        int m = tid + it * 256;
        if (m < NBLK) {
            int j  = m / W4_;
            int w4 = m - j * W4_;

            int ys = min(max(j + sy, 0), H_ - 1);
            int pp = 4 + w4 * 4 + sx;      // [0, 88]
            int q  = pp >> 2;
            int r  = pp & 3;               // warp-uniform (sx uniform per image)

            const float4* row4 = reinterpret_cast<const float4*>(&s[ys * RP_]);
            float4 A = row4[q];
            float4 v;
            if (r == 0) {
                v = A;
            } else {
                float4 B = row4[q + 1];
                if (r == 1)      v = make_float4(A.y, A.z, A.w, B.x);
                else if (r == 2) v = make_float4(A.z, A.w, B.x, B.y);
                else             v = make_float4(A.w, B.x, B.y, B.z);
            }
            out4[m] = v;
        }
    }
}

extern "C" void kernel_launch(void* const* d_in, const int* in_sizes, int n_in,
                              void* d_out, int out_size)
{
    const float* x     = (const float*)d_in[0];
    const int*   shift = (const int*)d_in[1];
    float*       out   = (float*)d_out;

    int n = in_sizes[0] / (C_ * H_ * W_);
    shift_smem_kernel<<<n * C_, 256>>>(x, shift, out);
}

// round 13
// speedup vs baseline: 1.3068x; 1.3068x over previous
#include <cuda_runtime.h>
#include <cstdint>

// RandomShiftsAug == integer pixel shift with edge clamp (reference's bilinear
// weights are exactly zero given its linspace/scale arithmetic):
//   out[n,c,j,i] = x[n,c, clamp(j+sy-PAD,0,H-1), clamp(i+sx-PAD,0,W-1)]
//
// R13: direct register swizzle (R5) + deep per-thread load batching (R3's
// MLP). One CTA per plane; each thread owns 7 quads in two batches (4+3):
// all clamped aligned LDG.128 of a batch issue back-to-back (MLP 8/6) before
// any consume, then compose with the warp-uniform shift r=sx&3 and store
// contiguous STG.128. No SMEM, no barriers; B loads skipped when r==0
// (uniform per image). Edge quads patched with register selects.

#define C_   4
#define W_   84
#define H_   84
#define PAD_ 4
#define W4_  21
#define NBLK (H_ * W4_)   // 1764 quads per plane

__device__ __forceinline__ float sel4(const float4& A, int i) {
    return (i <= 0) ? A.x : (i == 1) ? A.y : (i == 2) ? A.z : A.w;
}

template <int CNT>
__device__ __forceinline__ void do_batch(
    int it0, int tid, int sx, int sy, int r, int d,
    const float4* __restrict__ plane, float4* __restrict__ oplane)
{
    float4 A[CNT], B[CNT];
    int ww[CNT], mm[CNT];

    #pragma unroll
    for (int i = 0; i < CNT; ++i) {
        int m  = tid + (it0 + i) * 256;
        bool ok = (m < NBLK);
        int ms = ok ? m : 0;
        int j  = ms / W4_;
        int w4 = ms - j * W4_;
        mm[i] = m; ww[i] = w4;

        int ys = min(max(j + sy, 0), H_ - 1);
        const float4* row = plane + ys * W4_;
        int q = min(max(w4 + d, 0), W4_ - 1);

        A[i] = ok ? __ldg(row + q) : make_float4(0.f, 0.f, 0.f, 0.f);
        if (r)
            B[i] = ok ? __ldg(row + min(q + 1, W4_ - 1)) : A[i];
    }

    #pragma unroll
    for (int i = 0; i < CNT; ++i) {
        if (mm[i] < NBLK) {
            float4 v;
            if (r == 0)      v = A[i];
            else if (r == 1) v = make_float4(A[i].y, A[i].z, A[i].w, B[i].x);
            else if (r == 2) v = make_float4(A[i].z, A[i].w, B[i].x, B[i].y);
            else             v = make_float4(A[i].w, B[i].x, B[i].y, B[i].z);

            if (sx < 0 && ww[i] == 0) {
                // out[k] = in[max(k+sx,0)] = A[max(k+sx,0)]
                v.x = A[i].x;
                v.y = sel4(A[i], 1 + sx);
                v.z = sel4(A[i], 2 + sx);
                v.w = sel4(A[i], 3 + sx);
            } else if (sx > 0 && ww[i] == W4_ - 1) {
                // out[k] = in[80 + min(k+sx,3)] = A[min(k+sx,3)]
                v.x = sel4(A[i], min(0 + sx, 3));
                v.y = sel4(A[i], min(1 + sx, 3));
                v.z = sel4(A[i], min(2 + sx, 3));
                v.w = A[i].w;
            }
            oplane[mm[i]] = v;
        }
    }
}

__global__ void __launch_bounds__(256) shift_ilp_kernel(
    const float4* __restrict__ x4,
    const int*    __restrict__ shift,
    float4*       __restrict__ out4)
{
    const int nc  = blockIdx.x;        // n*C + c
    const int n   = nc >> 2;
    const int tid = threadIdx.x;

    int2 sh = __ldg(reinterpret_cast<const int2*>(shift) + n);
    const int sx = sh.x - PAD_;        // [-4, 4], uniform per image
    const int sy = sh.y - PAD_;
    const int r  = sx & 3;             // warp-uniform
    const int d  = (sx - r) >> 2;      // floor(sx/4) in {-1,0,1}

    const float4* plane  = x4  + nc * NBLK;
    float4*       oplane = out4 + nc * NBLK;

    do_batch<4>(0, tid, sx, sy, r, d, plane, oplane);
    do_batch<3>(4, tid, sx, sy, r, d, plane, oplane);
}

extern "C" void kernel_launch(void* const* d_in, const int* in_sizes, int n_in,
                              void* d_out, int out_size)
{
    const float4* x4    = (const float4*)d_in[0];
    const int*    shift = (const int*)d_in[1];
    float4*       out4  = (float4*)d_out;

    int n = in_sizes[0] / (C_ * H_ * W_);
    shift_ilp_kernel<<<n * C_, 256>>>(x4, shift, out4);
}